// round 16
// baseline (speedup 1.0000x reference)
#include <cuda_runtime.h>
#include <cuda_fp16.h>
#include <cstddef>
#include <cstdint>

#define NB   8
#define NQ   100
#define SH   128
#define SW   128
#define OH   512
#define OW   512
#define QPI  4            // queries per iteration
#define NIT  (NQ / QPI)   // 25

// bar.sync with a named barrier: 128 threads (one ph-group = 4 warps).
__device__ __forceinline__ void group_bar(int id) {
    asm volatile("bar.sync %0, 128;" :: "r"(id) : "memory");
}

// pack two f32 into f16x2 (lo = a, hi = b)
__device__ __forceinline__ uint32_t pack_h2(float a, float b) {
    uint32_t r;
    asm("cvt.rn.f16x2.f32 %0, %1, %2;" : "=r"(r) : "f"(b), "f"(a));
    return r;
}
__device__ __forceinline__ uint32_t tanh_h2(uint32_t x) {
    uint32_t r;
    asm("tanh.approx.f16x2 %0, %1;" : "=r"(r) : "r"(x));
    return r;
}

// Grid: (128 row-blocks k, 8 batches). Block: 512 threads, 3 CTAs/SM.
// R15 structure (GMEM-direct vertical, per-ph-group named barriers, one
// bar/iter), with the 4 scalar MUFU tanh per e replaced by 2x tanh.approx.f16x2
// (halves MUFU cycles, the dominant pipe per the R14/R15 cycle model).
__global__ __launch_bounds__(512, 3)
void m2f_fused_kernel(const float* __restrict__ cls,
                      const float* __restrict__ masks,
                      float* __restrict__ out)
{
    const int k = blockIdx.x;
    const int b = blockIdx.y;
    const int t = threadIdx.x;

    __shared__ __align__(16) float  vrow[2][QPI][4][SW];  // halved vertical lerps
    __shared__ __align__(16) float2 wts[NQ];              // pre-halved weights
    __shared__ float2 wsumg[4];                           // per-group weight sums

    // ---- per-CTA class softmax (halved) ----
    if (t < NQ) {
        const float* p = cls + ((size_t)b * NQ + t) * 3;
        float x0 = p[0], x1 = p[1], x2 = p[2];
        float m  = fmaxf(x0, fmaxf(x1, x2));
        float e0 = __expf(x0 - m), e1 = __expf(x1 - m), e2 = __expf(x2 - m);
        float inv = 0.5f / (e0 + e1 + e2);
        wts[t] = make_float2(e0 * inv, e1 * inv);
    }

    // clamped source rows
    const int r0 = (k == 0)      ? 0        : (k - 1);
    const int r2 = (k == SH - 1) ? (SH - 1) : (k + 1);
    const float* mb = masks + (size_t)b * NQ * SH * SW;
    const size_t qstride = (size_t)SH * SW;     // floats per query
    const size_t qf4     = qstride / 4;         // float4s per query

    // shared role keys: ph = t>>7 (row phase / group id), kx = t&127
    const int ph  = t >> 7;
    const int kx  = t & 127;
    const float vf = (ph == 0) ? 0.625f : (ph == 1) ? 0.875f
                   : (ph == 2) ? 0.125f : 0.375f;
    const int rowA = (ph < 2) ? r0 : k;
    const int rowB = (ph < 2) ? k  : r2;
    const int kxm = (kx == 0)      ? 0        : kx - 1;
    const int kxp = (kx == SW - 1) ? (SW - 1) : kx + 1;

    // vertical role: warp w -> (e = w&3, group ph = w>>2); lane -> 4-col group
    const int wid = t >> 5;
    const int ev  = wid & 3;
    const int c4g = t & 31;
    const float4* pA = reinterpret_cast<const float4*>(
        mb + (size_t)ev * qstride + (size_t)rowA * SW) + c4g;
    const float4* pB = reinterpret_cast<const float4*>(
        mb + (size_t)ev * qstride + (size_t)rowB * SW) + c4g;

    // ---- prologue: vertical quad 0 -> vrow[0] ----
    {
        float4 la = __ldg(pA);
        float4 lb = __ldg(pB);
        float4 r;
        r.x = 0.5f * fmaf(vf, lb.x - la.x, la.x);
        r.y = 0.5f * fmaf(vf, lb.y - la.y, la.y);
        r.z = 0.5f * fmaf(vf, lb.z - la.z, la.z);
        r.w = 0.5f * fmaf(vf, lb.w - la.w, la.w);
        *reinterpret_cast<float4*>(&vrow[0][ev][ph][4 * c4g]) = r;
        pA += QPI * qf4;
        pB += QPI * qf4;
    }

    __syncthreads();   // wts + vrow[0] published block-wide

    // per-group weight sum by the group's leader warp (wid = 4*ph).
    if ((wid & 3) == 0) {
        const int lane = t & 31;
        float sx = 0.f, sy = 0.f;
        for (int q = lane; q < NQ; q += 32) { sx += wts[q].x; sy += wts[q].y; }
        #pragma unroll
        for (int o = 16; o > 0; o >>= 1) {
            sx += __shfl_down_sync(0xFFFFFFFFu, sx, o);
            sy += __shfl_down_sync(0xFFFFFFFFu, sy, o);
        }
        if (lane == 0) wsumg[wid >> 2] = make_float2(sx, sy);
    }

    float acc0[4] = {0.f,0.f,0.f,0.f};
    float acc1[4] = {0.f,0.f,0.f,0.f};
    const float4* wv = reinterpret_cast<const float4*>(wts);
    const int bar_id = ph + 1;

    #pragma unroll 2
    for (int j = 0; j < NIT; j++) {
        const int bs = j & 1;
        const int nb = bs ^ 1;

        // issue LDG for quad j+1 first (hidden under horizontal compute)
        float4 la, lb;
        const bool dv = (j + 1 < NIT);
        if (dv) {
            la = __ldg(pA);
            lb = __ldg(pB);
        }

        // horizontal: quad j from vrow[bs]
        {
            const float4 wA = wv[2*j];
            const float4 wB = wv[2*j+1];
            const float wxa[4] = {wA.x, wA.z, wB.x, wB.z};
            const float wya[4] = {wA.y, wA.w, wB.y, wB.w};

            #pragma unroll
            for (int e = 0; e < QPI; e++) {
                const float vL = vrow[bs][e][ph][kxm];
                const float vM = vrow[bs][e][ph][kx];
                const float vR = vrow[bs][e][ph][kxp];
                const float dl = vM - vL;
                const float dr = vR - vM;

                const float h0 = fmaf(0.625f, dl, vL);
                const float h1 = fmaf(0.875f, dl, vL);
                const float h2 = fmaf(0.125f, dr, vM);
                const float h3 = fmaf(0.375f, dr, vM);

                // 2x f16x2 tanh instead of 4x f32 tanh (halves MUFU)
                const uint32_t p01 = tanh_h2(pack_h2(h0, h1));
                const uint32_t p23 = tanh_h2(pack_h2(h2, h3));
                const __half2 th01 = *reinterpret_cast<const __half2*>(&p01);
                const __half2 th23 = *reinterpret_cast<const __half2*>(&p23);
                const float2 t01 = __half22float2(th01);
                const float2 t23 = __half22float2(th23);

                const float wx = wxa[e], wy = wya[e];
                acc0[0] = fmaf(wx, t01.x, acc0[0]);
                acc0[1] = fmaf(wx, t01.y, acc0[1]);
                acc0[2] = fmaf(wx, t23.x, acc0[2]);
                acc0[3] = fmaf(wx, t23.y, acc0[3]);
                acc1[0] = fmaf(wy, t01.x, acc1[0]);
                acc1[1] = fmaf(wy, t01.y, acc1[1]);
                acc1[2] = fmaf(wy, t23.x, acc1[2]);
                acc1[3] = fmaf(wy, t23.y, acc1[3]);
            }
        }

        // vertical: quad j+1 -> vrow[nb]
        if (dv) {
            float4 r;
            r.x = 0.5f * fmaf(vf, lb.x - la.x, la.x);
            r.y = 0.5f * fmaf(vf, lb.y - la.y, la.y);
            r.z = 0.5f * fmaf(vf, lb.z - la.z, la.z);
            r.w = 0.5f * fmaf(vf, lb.w - la.w, la.w);
            *reinterpret_cast<float4*>(&vrow[nb][ev][ph][4 * c4g]) = r;
            pA += QPI * qf4;
            pB += QPI * qf4;
        }
        group_bar(bar_id);
    }

    // out[b][c][4k+ph][4kx + 0..3] = acc + Sum(w/2)
    const float2 S = wsumg[ph];
    const int y = 4 * k + ph;
    float4 o0 = make_float4(acc0[0] + S.x, acc0[1] + S.x,
                            acc0[2] + S.x, acc0[3] + S.x);
    float4 o1 = make_float4(acc1[0] + S.y, acc1[1] + S.y,
                            acc1[2] + S.y, acc1[3] + S.y);
    const size_t base0 = (((size_t)b * 2 + 0) * OH + y) * OW + 4 * kx;
    const size_t base1 = (((size_t)b * 2 + 1) * OH + y) * OW + 4 * kx;
    *reinterpret_cast<float4*>(out + base0) = o0;
    *reinterpret_cast<float4*>(out + base1) = o1;
}

extern "C" void kernel_launch(void* const* d_in, const int* in_sizes, int n_in,
                              void* d_out, int out_size)
{
    const float* cls   = (const float*)d_in[0];  // [8,100,3]
    const float* masks = (const float*)d_in[1];  // [8,100,128,128]
    float*       out   = (float*)d_out;          // [8,2,512,512]

    dim3 grid(SH, NB);
    dim3 block(512);
    m2f_fused_kernel<<<grid, block>>>(cls, masks, out);
}

// round 17
// speedup vs baseline: 1.0638x; 1.0638x over previous
#include <cuda_runtime.h>
#include <cstddef>
#include <cstdint>

#define NB   8
#define NQ   100
#define SH   128
#define SW   128
#define OH   512
#define OW   512
#define QPI  4            // queries per iteration
#define NIT  (NQ / QPI)   // 25

__device__ __forceinline__ float fast_tanh(float x) {
    float r;
    asm("tanh.approx.f32 %0, %1;" : "=f"(r) : "f"(x));
    return r;
}

__device__ __forceinline__ void cp_async16(uint32_t dst_smem, const void* src) {
    asm volatile("cp.async.cg.shared.global [%0], [%1], 16;"
                 :: "r"(dst_smem), "l"(src));
}
__device__ __forceinline__ void cp_commit() {
    asm volatile("cp.async.commit_group;" ::: "memory");
}
__device__ __forceinline__ void cp_wait0() {
    asm volatile("cp.async.wait_group 0;" ::: "memory");
}

// Grid: (128 row-blocks k, 8 batches). Block: 512 threads, 4 CTAs/SM (2048 thr
// = full occupancy; launch_bounds forces <=32 regs, enabled by cp.async
// staging that holds NO registers for in-flight loads).
// Ring: buf[2] quads staged by cp.async (3 unique source rows per query);
//   iter j: stage(quad j+2 -> buf[j&1]) || horizontal(quad j from vrow[j&1])
//           || vertical(quad j+1 from buf[~] -> vrow[~]); wait+ONE syncthreads.
__global__ __launch_bounds__(512, 4)
void m2f_fused_kernel(const float* __restrict__ cls,
                      const float* __restrict__ masks,
                      float* __restrict__ out)
{
    const int k = blockIdx.x;
    const int b = blockIdx.y;
    const int t = threadIdx.x;

    __shared__ __align__(16) float  buf[2][QPI][3][SW];   // raw staged rows
    __shared__ __align__(16) float  vrow[2][QPI][4][SW];  // halved vertical lerps
    __shared__ __align__(16) float2 wts[NQ];              // pre-halved weights
    __shared__ float2 wsum;

    // ---- per-CTA class softmax (halved) ----
    if (t < NQ) {
        const float* p = cls + ((size_t)b * NQ + t) * 3;
        float x0 = p[0], x1 = p[1], x2 = p[2];
        float m  = fmaxf(x0, fmaxf(x1, x2));
        float e0 = __expf(x0 - m), e1 = __expf(x1 - m), e2 = __expf(x2 - m);
        float inv = 0.5f / (e0 + e1 + e2);
        wts[t] = make_float2(e0 * inv, e1 * inv);
    }

    // clamped source rows
    const int r0 = (k == 0)      ? 0        : (k - 1);
    const int r2 = (k == SH - 1) ? (SH - 1) : (k + 1);
    const float* mb = masks + (size_t)b * NQ * SH * SW;
    const size_t qstride = (size_t)SH * SW;     // floats per query

    // staging role: 384 threads (warps 0..11), one 16B cp.async each per iter
    const bool stager = (t < 384);
    const int  wid = t >> 5;
    const int  sq  = wid / 3;           // query-in-quad 0..3 (stagers)
    const int  rr  = wid % 3;           // row 0..2 -> (r0, k, r2)
    const int  c4  = t & 31;
    const int  stg_row = (rr == 0) ? r0 : ((rr == 1) ? k : r2);
    const float* gp = mb + (size_t)sq * qstride + (size_t)stg_row * SW + 4 * c4;
    const uint32_t dst0 = (uint32_t)__cvta_generic_to_shared(&buf[0][sq][rr][4 * c4]);
    const uint32_t dst1 = dst0 + (uint32_t)(QPI * 3 * SW * sizeof(float));

    // shared role keys: ph = t>>7 (row phase), kx = t&127
    const int ph  = t >> 7;
    const int kx  = t & 127;
    const float vf = (ph == 0) ? 0.625f : (ph == 1) ? 0.875f
                   : (ph == 2) ? 0.125f : 0.375f;
    const int ra  = (ph < 2) ? 0 : 1;      // row index within buf's 3 rows
    const int rb  = ra + 1;
    const int kxm = (kx == 0)      ? 0        : kx - 1;
    const int kxp = (kx == SW - 1) ? (SW - 1) : kx + 1;

    // vertical role: warp wid -> (e = wid&3, ph = wid>>2); lane -> 4-col group
    const int ev  = wid & 3;
    const int c4g = t & 31;

    // ---- prologue: stage quads 0 and 1 via cp.async ----
    if (stager) {
        cp_async16(dst0, gp);
        cp_commit();
        cp_async16(dst1, gp + QPI * qstride);
        cp_commit();
        gp += 2 * QPI * qstride;           // next: quad 2
        cp_wait0();
    }
    __syncthreads();   // wts + buf[0..1] visible

    // weight sum (halved) by warp 0 (after wts is published)
    if (t < 32) {
        float sx = 0.f, sy = 0.f;
        for (int q = t; q < NQ; q += 32) { sx += wts[q].x; sy += wts[q].y; }
        #pragma unroll
        for (int o = 16; o > 0; o >>= 1) {
            sx += __shfl_down_sync(0xFFFFFFFFu, sx, o);
            sy += __shfl_down_sync(0xFFFFFFFFu, sy, o);
        }
        if (t == 0) wsum = make_float2(sx, sy);
    }

    // vertical quad 0 -> vrow[0]
    {
        const float4 a  = *reinterpret_cast<const float4*>(&buf[0][ev][ra][4 * c4g]);
        const float4 bb = *reinterpret_cast<const float4*>(&buf[0][ev][rb][4 * c4g]);
        float4 r;
        r.x = 0.5f * fmaf(vf, bb.x - a.x, a.x);
        r.y = 0.5f * fmaf(vf, bb.y - a.y, a.y);
        r.z = 0.5f * fmaf(vf, bb.z - a.z, a.z);
        r.w = 0.5f * fmaf(vf, bb.w - a.w, a.w);
        *reinterpret_cast<float4*>(&vrow[0][ev][ph][4 * c4g]) = r;
    }
    __syncthreads();

    float acc0[4] = {0.f,0.f,0.f,0.f};
    float acc1[4] = {0.f,0.f,0.f,0.f};

    #pragma unroll 2
    for (int j = 0; j < NIT; j++) {
        const int bs = j & 1;
        const int nb = bs ^ 1;

        // stage quad j+2 -> buf[bs] (its quad-j data died at iter j-1)
        const bool ds = stager && (j + 2 < NIT);
        if (ds) {
            cp_async16(bs ? dst1 : dst0, gp);
            cp_commit();
            gp += QPI * qstride;
        }

        // horizontal: quad j from vrow[bs]
        #pragma unroll
        for (int e = 0; e < QPI; e++) {
            const float2 w  = wts[QPI * j + e];
            const float  vL = vrow[bs][e][ph][kxm];
            const float  vM = vrow[bs][e][ph][kx];
            const float  vR = vrow[bs][e][ph][kxp];
            const float  dl = vM - vL;
            const float  dr = vR - vM;

            float t0 = fast_tanh(fmaf(0.625f, dl, vL));
            float t1 = fast_tanh(fmaf(0.875f, dl, vL));
            float t2 = fast_tanh(fmaf(0.125f, dr, vM));
            float t3 = fast_tanh(fmaf(0.375f, dr, vM));

            acc0[0] = fmaf(w.x, t0, acc0[0]);
            acc0[1] = fmaf(w.x, t1, acc0[1]);
            acc0[2] = fmaf(w.x, t2, acc0[2]);
            acc0[3] = fmaf(w.x, t3, acc0[3]);
            acc1[0] = fmaf(w.y, t0, acc1[0]);
            acc1[1] = fmaf(w.y, t1, acc1[1]);
            acc1[2] = fmaf(w.y, t2, acc1[2]);
            acc1[3] = fmaf(w.y, t3, acc1[3]);
        }

        // vertical: quad j+1 from buf[nb] -> vrow[nb]
        if (j + 1 < NIT) {
            const float4 a  = *reinterpret_cast<const float4*>(&buf[nb][ev][ra][4 * c4g]);
            const float4 bb = *reinterpret_cast<const float4*>(&buf[nb][ev][rb][4 * c4g]);
            float4 r;
            r.x = 0.5f * fmaf(vf, bb.x - a.x, a.x);
            r.y = 0.5f * fmaf(vf, bb.y - a.y, a.y);
            r.z = 0.5f * fmaf(vf, bb.z - a.z, a.z);
            r.w = 0.5f * fmaf(vf, bb.w - a.w, a.w);
            *reinterpret_cast<float4*>(&vrow[nb][ev][ph][4 * c4g]) = r;
        }

        // quad j+2 must be resident before B(j): ample slack (issued at iter top)
        if (ds) cp_wait0();
        __syncthreads();
    }

    // out[b][c][4k+ph][4kx + 0..3] = acc + Sum(w/2)
    const float2 S = wsum;
    const int y = 4 * k + ph;
    float4 o0 = make_float4(acc0[0] + S.x, acc0[1] + S.x,
                            acc0[2] + S.x, acc0[3] + S.x);
    float4 o1 = make_float4(acc1[0] + S.y, acc1[1] + S.y,
                            acc1[2] + S.y, acc1[3] + S.y);
    const size_t base0 = (((size_t)b * 2 + 0) * OH + y) * OW + 4 * kx;
    const size_t base1 = (((size_t)b * 2 + 1) * OH + y) * OW + 4 * kx;
    *reinterpret_cast<float4*>(out + base0) = o0;
    *reinterpret_cast<float4*>(out + base1) = o1;
}

extern "C" void kernel_launch(void* const* d_in, const int* in_sizes, int n_in,
                              void* d_out, int out_size)
{
    const float* cls   = (const float*)d_in[0];  // [8,100,3]
    const float* masks = (const float*)d_in[1];  // [8,100,128,128]
    float*       out   = (float*)d_out;          // [8,2,512,512]

    dim3 grid(SH, NB);
    dim3 block(512);
    m2f_fused_kernel<<<grid, block>>>(cls, masks, out);
}